// round 14
// baseline (speedup 1.0000x reference)
#include <cuda_runtime.h>
#include <cuda_fp16.h>
#include <cuda_bf16.h>
#include <cstdint>

// Problem constants
#define BB 8
#define CC_ 256
#define OO 256
#define HH 64
#define WW 64
#define HWSZ 4096
#define PLANE (HH*WW*CC_)
#define K9 9

// ---------------- scratch (static __device__ — no allocation) ----------------
__device__ float  g_xT[BB * PLANE];           // x in NHWC fp32 (offset conv)
__device__ __half g_xH[BB * PLANE];           // x in NHWC fp16 (gather)
__device__ float g_py[BB * K9 * HWSZ];
__device__ float g_px[BB * K9 * HWSZ];
// main-conv B images, swizzled fp16: [tap*4+ch] -> [o:256][c:64] (32KB each)
__device__ uint4 g_wB[K9 * 4 * 2048];
// offset-conv B images, swizzled bf16 hi/lo: [chunk=tap*4+ch] -> [n:32][k:64] (4KB each)
__device__ uint4 g_oBhi[36 * 256];
__device__ uint4 g_oBlo[36 * 256];

// ---------------- helpers ----------------
__device__ __forceinline__ unsigned smem_u32(const void* p) {
    unsigned a;
    asm("{ .reg .u64 t; cvta.to.shared.u64 t, %1; cvt.u32.u64 %0, t; }" : "=r"(a) : "l"(p));
    return a;
}
__device__ __forceinline__ void ldsm4(unsigned& r0, unsigned& r1, unsigned& r2, unsigned& r3, unsigned addr) {
    asm volatile("ldmatrix.sync.aligned.m8n8.x4.shared.b16 {%0,%1,%2,%3}, [%4];"
                 : "=r"(r0), "=r"(r1), "=r"(r2), "=r"(r3) : "r"(addr));
}
__device__ __forceinline__ void mma16816(float* d, unsigned a0, unsigned a1, unsigned a2, unsigned a3,
                                         unsigned b0, unsigned b1) {
    asm volatile("mma.sync.aligned.m16n8k16.row.col.f32.f16.f16.f32 "
                 "{%0,%1,%2,%3}, {%4,%5,%6,%7}, {%8,%9}, {%0,%1,%2,%3};"
                 : "+f"(d[0]), "+f"(d[1]), "+f"(d[2]), "+f"(d[3])
                 : "r"(a0), "r"(a1), "r"(a2), "r"(a3), "r"(b0), "r"(b1));
}
__device__ __forceinline__ void mma16816bf(float* d, unsigned a0, unsigned a1, unsigned a2, unsigned a3,
                                           unsigned b0, unsigned b1) {
    asm volatile("mma.sync.aligned.m16n8k16.row.col.f32.bf16.bf16.f32 "
                 "{%0,%1,%2,%3}, {%4,%5,%6,%7}, {%8,%9}, {%0,%1,%2,%3};"
                 : "+f"(d[0]), "+f"(d[1]), "+f"(d[2]), "+f"(d[3])
                 : "r"(a0), "r"(a1), "r"(a2), "r"(a3), "r"(b0), "r"(b1));
}
__device__ __forceinline__ void cp16(unsigned dst, const void* src) {
    asm volatile("cp.async.cg.shared.global [%0], [%1], 16;" :: "r"(dst), "l"(src));
}
__device__ __forceinline__ unsigned pack_h2(float a, float b) {
    __half2 t = __floats2half2_rn(a, b);
    return *(unsigned*)&t;
}
__device__ __forceinline__ unsigned pack_bf2(float a, float b) {
    __nv_bfloat162 t; t.x = __float2bfloat16(a); t.y = __float2bfloat16(b);
    return *(unsigned*)&t;
}
__device__ __forceinline__ unsigned long long pack2(float v) {
    unsigned long long r; asm("mov.b64 %0, {%1, %1};" : "=l"(r) : "f"(v)); return r;
}
__device__ __forceinline__ unsigned long long packf2(float2 v) {
    unsigned long long r; asm("mov.b64 %0, {%1, %2};" : "=l"(r) : "f"(v.x), "f"(v.y)); return r;
}
__device__ __forceinline__ unsigned long long fma2(unsigned long long a, unsigned long long b, unsigned long long c) {
    unsigned long long d; asm("fma.rn.f32x2 %0, %1, %2, %3;" : "=l"(d) : "l"(a), "l"(b), "l"(c)); return d;
}
__device__ __forceinline__ unsigned h2_from_f2(unsigned long long v) {
    unsigned r; float lo, hi;
    asm("mov.b64 {%0, %1}, %2;" : "=f"(lo), "=f"(hi) : "l"(v));
    asm("cvt.rn.f16x2.f32 %0, %2, %1;" : "=r"(r) : "f"(lo), "f"(hi));
    return r;
}
__device__ __forceinline__ void samp(float py, float px, int4& id, float4& wv) {
    float fy = floorf(py), fx = floorf(px);
    int iy0 = (int)fy, ix0 = (int)fx;
    float wy1 = py - fy, wx1 = px - fx;
    float wy0 = 1.f - wy1, wx0 = 1.f - wx1;
    int iy1 = iy0 + 1, ix1 = ix0 + 1;
    bool vy0 = (iy0 >= 0) && (iy0 < HH), vy1 = (iy1 >= 0) && (iy1 < HH);
    bool vx0 = (ix0 >= 0) && (ix0 < WW), vx1 = (ix1 >= 0) && (ix1 < WW);
    int cy0 = min(max(iy0, 0), HH - 1), cy1 = min(max(iy1, 0), HH - 1);
    int cx0 = min(max(ix0, 0), WW - 1), cx1 = min(max(ix1, 0), WW - 1);
    id = make_int4(((cy0 << 6) + cx0) << 8, ((cy0 << 6) + cx1) << 8,
                   ((cy1 << 6) + cx0) << 8, ((cy1 << 6) + cx1) << 8);
    wv = make_float4((vy0 && vx0) ? wy0 * wx0 : 0.f, (vy0 && vx1) ? wy0 * wx1 : 0.f,
                     (vy1 && vx0) ? wy1 * wx0 : 0.f, (vy1 && vx1) ? wy1 * wx1 : 0.f);
}

// ---------------- kernel 1: fused NCHW->NHWC transpose (fp32+fp16) + weight prep ----------------
#define TXP_BLOCKS (BB * HH * 2)
__global__ __launch_bounds__(256) void k_txp_prep(const float* __restrict__ x,
                                                  const float* __restrict__ conv_w,
                                                  const float* __restrict__ offw) {
    if (blockIdx.x < TXP_BLOCKS) {
        __shared__ float t[128][65];
        int b = blockIdx.x >> 7;
        int y = (blockIdx.x >> 1) & 63;
        int h = blockIdx.x & 1;
        for (int i = threadIdx.x; i < 128 * 64; i += 256) {
            int c = i >> 6, xx = i & 63;
            t[c][xx] = x[(((b << 8) + (h << 7) + c) << 12) + (y << 6) + xx];
        }
        __syncthreads();
        for (int i = threadIdx.x; i < 64 * 128; i += 256) {
            int xx = i >> 7, c = i & 127;
            float v = t[c][xx];
            size_t o = ((((size_t)(b << 6) + y) << 6) + xx) * 256 + (h << 7) + c;
            g_xT[o] = v;
            g_xH[o] = __float2half_rn(v);
        }
        return;
    }
    int idx = (blockIdx.x - TXP_BLOCKS) * 256 + threadIdx.x;
    if (idx < K9 * 4 * 256 * 64) {
        int c   = idx & 63;
        int o   = (idx >> 6) & 255;
        int ch  = (idx >> 14) & 3;
        int tap = idx >> 16;
        float f = conv_w[(o * 256 + (ch << 6) + c) * 9 + tap];
        int img = tap * 4 + ch;
        unsigned off = (unsigned)((o << 7) + (c << 1));
        off ^= (unsigned)((o & 7) << 4);               // ldmatrix-friendly XOR swizzle
        ((__half*)g_wB)[img * 16384 + (off >> 1)] = __float2half_rn(f);
    }
    int j = idx - K9 * 4 * 256 * 64;
    if (j >= 0 && j < 36 * 32 * 64) {
        int kk    = j & 63;
        int n     = (j >> 6) & 31;
        int chunk = j >> 11;             // tap*4+ch
        int tap   = chunk >> 2;
        int ch    = chunk & 3;
        float f = (n < 18) ? offw[(n * 256 + (ch << 6) + kk) * 9 + tap] : 0.f;
        __nv_bfloat16 hi = __float2bfloat16(f);
        __nv_bfloat16 lo = __float2bfloat16(f - __bfloat162float(hi));
        unsigned off = (unsigned)((n << 7) + (kk << 1));
        off ^= (unsigned)((n & 7) << 4);
        ((__nv_bfloat16*)g_oBhi)[chunk * 2048 + (off >> 1)] = hi;
        ((__nv_bfloat16*)g_oBlo)[chunk * 2048 + (off >> 1)] = lo;
    }
}

// ---------------- kernel 2: offset conv, panel-staged A + 3-pass bf16 HMMA ----------------
// block = (b, row-pair): M=128 px, N=24 used (pad 32), K = 4 ch-chunks x 64.
// A panel: 4 rows x 66 cols x 64ch staged ONCE per ch-chunk; 9 taps read shifted addresses.
#define OFP_HI   0
#define OFP_LO   33792
#define OFP_B    67584
#define OFP_TOT  83968

__global__ __launch_bounds__(256, 2) void k_offs(const float* __restrict__ offb) {
    extern __shared__ char smem[];
    unsigned sb = smem_u32(smem);
    int tid = threadIdx.x;
    int w = tid >> 5, lid = tid & 31;
    int b = blockIdx.x >> 5;
    int y0 = (blockIdx.x & 31) << 1;

    const float* plane = g_xT + ((size_t)b << 20);
    int r = w >> 2;                      // output row within pair
    int cbase = (w & 3) << 4;            // col base of warp's 16-pixel strip
    unsigned xorS = (unsigned)((lid & 7) << 4);
    unsigned bBase = (unsigned)(((lid & 7) + ((lid & 16) ? 8 : 0)) << 7)
                   + (unsigned)(((lid >> 3) & 1) << 4);

    float acc[3][4];
#pragma unroll
    for (int nf = 0; nf < 3; ++nf)
#pragma unroll
        for (int q = 0; q < 4; ++q) acc[nf][q] = 0.f;

    // prologue: B(t=0)
    {
        cp16(sb + OFP_B + (tid << 4), g_oBhi + tid);
        cp16(sb + OFP_B + 4096 + (tid << 4), g_oBlo + tid);
        asm volatile("cp.async.commit_group;" ::: "memory");
    }
    // stage panel for ch=0
    {
        for (int p = tid; p < 264; p += 256) {
            int row = p / 66, col = p - row * 66;
            int yy = y0 - 1 + row, xx = col - 1;
            bool ok = (yy >= 0) && (yy < HH) && (xx >= 0) && (xx < WW);
            const float* src = plane + ((yy << 6) + xx) * 256;
            unsigned pb = (unsigned)(p << 7);
            unsigned sw = (unsigned)((p & 7) << 4);
#pragma unroll
            for (int j = 0; j < 16; ++j) {
                float4 v = ok ? *(const float4*)(src + (j << 2)) : make_float4(0.f, 0.f, 0.f, 0.f);
                __nv_bfloat16 h0 = __float2bfloat16(v.x), h1 = __float2bfloat16(v.y);
                __nv_bfloat16 h2 = __float2bfloat16(v.z), h3 = __float2bfloat16(v.w);
                uint2 uh, ul;
                { __nv_bfloat162 t0; t0.x = h0; t0.y = h1; uh.x = *(unsigned*)&t0;
                  __nv_bfloat162 t1; t1.x = h2; t1.y = h3; uh.y = *(unsigned*)&t1; }
                ul.x = pack_bf2(v.x - __bfloat162float(h0), v.y - __bfloat162float(h1));
                ul.y = pack_bf2(v.z - __bfloat162float(h2), v.w - __bfloat162float(h3));
                unsigned off = pb + (unsigned)((j << 3) ^ sw);
                *(uint2*)(smem + OFP_HI + off) = uh;
                *(uint2*)(smem + OFP_LO + off) = ul;
            }
        }
    }

    for (int t = 0; t < 36; ++t) {
        int ch = t / 9, tap = t - ch * 9;
        // commit B(t+1)
        if (t < 35) {
            int t1 = t + 1;
            int chk = (t1 - (t1 / 9) * 9) * 4 + (t1 / 9);
            unsigned dst = sb + OFP_B + (unsigned)((t1 & 1) << 13);
            cp16(dst + (tid << 4), g_oBhi + chk * 256 + tid);
            cp16(dst + 4096 + (tid << 4), g_oBlo + chk * 256 + tid);
            asm volatile("cp.async.commit_group;" ::: "memory");
        }
        // re-stage panel at each new ch-chunk
        if (tap == 0 && t > 0) {
            __syncthreads();             // all warps done reading old panel
            for (int p = tid; p < 264; p += 256) {
                int row = p / 66, col = p - row * 66;
                int yy = y0 - 1 + row, xx = col - 1;
                bool ok = (yy >= 0) && (yy < HH) && (xx >= 0) && (xx < WW);
                const float* src = plane + ((yy << 6) + xx) * 256 + (ch << 6);
                unsigned pb = (unsigned)(p << 7);
                unsigned sw = (unsigned)((p & 7) << 4);
#pragma unroll
                for (int j = 0; j < 16; ++j) {
                    float4 v = ok ? *(const float4*)(src + (j << 2)) : make_float4(0.f, 0.f, 0.f, 0.f);
                    __nv_bfloat16 h0 = __float2bfloat16(v.x), h1 = __float2bfloat16(v.y);
                    __nv_bfloat16 h2 = __float2bfloat16(v.z), h3 = __float2bfloat16(v.w);
                    uint2 uh, ul;
                    { __nv_bfloat162 t0; t0.x = h0; t0.y = h1; uh.x = *(unsigned*)&t0;
                      __nv_bfloat162 t1; t1.x = h2; t1.y = h3; uh.y = *(unsigned*)&t1; }
                    ul.x = pack_bf2(v.x - __bfloat162float(h0), v.y - __bfloat162float(h1));
                    ul.y = pack_bf2(v.z - __bfloat162float(h2), v.w - __bfloat162float(h3));
                    unsigned off = pb + (unsigned)((j << 3) ^ sw);
                    *(uint2*)(smem + OFP_HI + off) = uh;
                    *(uint2*)(smem + OFP_LO + off) = ul;
                }
            }
        }
        if (t < 35) { asm volatile("cp.async.wait_group 1;" ::: "memory"); }
        else        { asm volatile("cp.async.wait_group 0;" ::: "memory"); }
        __syncthreads();

        // ---- MMAs: 4 k16 steps, 3 passes, nf=0..2 ----
        int ty = tap / 3, tx = tap - ty * 3;
        int tb = (r + ty) * 66 + cbase + tx;
        unsigned bbuf = OFP_B + (unsigned)((t & 1) << 13);
#pragma unroll
        for (int ks = 0; ks < 4; ++ks) {
            unsigned p = (unsigned)(tb + (lid & 15));
            unsigned lin = (p << 7) + (unsigned)(ks << 5) + (unsigned)((lid >> 4) << 4);
            lin ^= (p & 7) << 4;
            unsigned ah0, ah1, ah2, ah3, al0, al1, al2, al3;
            ldsm4(ah0, ah1, ah2, ah3, sb + OFP_HI + lin);
            ldsm4(al0, al1, al2, al3, sb + OFP_LO + lin);
            unsigned bh[4][2], bl[4][2];
#pragma unroll
            for (int n16 = 0; n16 < 2; ++n16) {
                unsigned bln = (bBase + (unsigned)(ks << 5) + (unsigned)(n16 << 11)) ^ xorS;
                unsigned q0, q1, q2, q3;
                ldsm4(q0, q1, q2, q3, sb + bbuf + bln);
                bh[n16 * 2 + 0][0] = q0; bh[n16 * 2 + 0][1] = q1;
                bh[n16 * 2 + 1][0] = q2; bh[n16 * 2 + 1][1] = q3;
                ldsm4(q0, q1, q2, q3, sb + bbuf + 4096 + bln);
                bl[n16 * 2 + 0][0] = q0; bl[n16 * 2 + 0][1] = q1;
                bl[n16 * 2 + 1][0] = q2; bl[n16 * 2 + 1][1] = q3;
            }
#pragma unroll
            for (int nf = 0; nf < 3; ++nf) {
                mma16816bf(acc[nf], ah0, ah1, ah2, ah3, bh[nf][0], bh[nf][1]);
                mma16816bf(acc[nf], ah0, ah1, ah2, ah3, bl[nf][0], bl[nf][1]);
                mma16816bf(acc[nf], al0, al1, al2, al3, bh[nf][0], bh[nf][1]);
            }
        }
    }

    // ---- epilogue: coords = base + offset + bias ----
#pragma unroll
    for (int nf = 0; nf < 3; ++nf) {
        int k = (nf << 2) + (lid & 3);
        if (k < 9) {
            float oy = offb[2 * k], ox = offb[2 * k + 1];
            int ky = k / 3, kx = k - ky * 3;
#pragma unroll
            for (int h = 0; h < 2; ++h) {
                int m = (w << 4) + (lid >> 2) + (h << 3);
                int ym = y0 + (m >> 6), xm = m & 63;
                int gi = ((b * 9 + k) << 12) + (ym << 6) + xm;
                g_py[gi] = (float)(ym - 1 + ky) + acc[nf][h * 2]     + oy;
                g_px[gi] = (float)(xm - 1 + kx) + acc[nf][h * 2 + 1] + ox;
            }
        }
    }
}

// ---------------- kernel 3: fused fp16 gather + single-pass fp16 HMMA GEMM ----------------
// block = (b, y): M=64 pixels, N=256 outputs; 8 warps 2Mx4N, 32x64 warp tiles.
// smem: A double 2x8KB + B double 2x32KB = 80KB; 2 CTAs/SM.
#define SM_A     0
#define SM_B     16384
#define SM_TOTAL 81920

__global__ __launch_bounds__(256, 2) void k_main(float* __restrict__ out) {
    extern __shared__ char smem[];
    unsigned sb = smem_u32(smem);
    int tid = threadIdx.x;
    int w = tid >> 5, lid = tid & 31;
    int b = blockIdx.x >> 6;
    int y = blockIdx.x & 63;

    const __half* planeH = g_xH + ((size_t)b << 20);
    int mA = tid >> 2;                    // staging pixel 0..63
    int cq = (tid & 3) << 4;              // 16-chan strip within 64-chunk
    unsigned xm = (unsigned)((mA & 7) << 4);
    int gi0 = ((b * 9) << 12) + (y << 6) + mA;

    int warpM = w >> 2, warpN = w & 3;
    unsigned xorS  = (unsigned)((lid & 7) << 4);
    unsigned aBase = (unsigned)(((warpM << 5) + (lid & 15)) << 7) + (unsigned)((lid >> 4) << 4);
    unsigned bBase = (unsigned)(((warpN << 6) + (lid & 7) + ((lid & 16) ? 8 : 0)) << 7)
                   + (unsigned)(((lid >> 3) & 1) << 4);

    float acc[2][8][4];
#pragma unroll
    for (int mi = 0; mi < 2; ++mi)
#pragma unroll
        for (int nf = 0; nf < 8; ++nf)
#pragma unroll
            for (int q = 0; q < 4; ++q) acc[mi][nf][q] = 0.f;

    // ---- prologue: stage iter 0 (tap0, ch0) into buffer 0; pre-sample t=1 ----
    int4 idC; float4 wvC;                 // carried sampling state for NEXT staging
    {
#pragma unroll
        for (int i = 0; i < 8; ++i)
            cp16(sb + SM_B + ((tid + i * 256) << 4), g_wB + tid + i * 256);
        asm volatile("cp.async.commit_group;" ::: "memory");
        int4 id; float4 wv;
        samp(g_py[gi0], g_px[gi0], id, wv);
        const __half* pbh = planeH + cq;
        unsigned long long w0 = pack2(wv.x), w1 = pack2(wv.y), w2 = pack2(wv.z), w3 = pack2(wv.w);
#pragma unroll
        for (int seg = 0; seg < 2; ++seg) {
            const __half* p4 = pbh + (seg << 3);
            uint4 u0 = *(const uint4*)(p4 + id.x);
            uint4 u1 = *(const uint4*)(p4 + id.y);
            uint4 u2 = *(const uint4*)(p4 + id.z);
            uint4 u3 = *(const uint4*)(p4 + id.w);
            uint4 st;
#pragma unroll
            for (int q = 0; q < 4; ++q) {
                unsigned long long f0 = packf2(__half22float2(((const __half2*)&u0)[q]));
                unsigned long long f1 = packf2(__half22float2(((const __half2*)&u1)[q]));
                unsigned long long f2 = packf2(__half22float2(((const __half2*)&u2)[q]));
                unsigned long long f3 = packf2(__half22float2(((const __half2*)&u3)[q]));
                unsigned long long s2 = fma2(w0, f0, fma2(w1, f1, fma2(w2, f2, fma2(w3, f3, 0ull))));
                ((unsigned*)&st)[q] = h2_from_f2(s2);
            }
            unsigned off = ((unsigned)(mA << 7) + (unsigned)((cq + (seg << 3)) << 1)) ^ xm;
            *(uint4*)(smem + SM_A + off) = st;
        }
        // pre-sample t=1 (tap1, ch0) and prefetch its corner lines
        samp(g_py[gi0 + (1 << 12)], g_px[gi0 + (1 << 12)], idC, wvC);
        if ((tid & 3) == 0) {
            asm volatile("prefetch.global.L1 [%0];" :: "l"(planeH + idC.x));
            asm volatile("prefetch.global.L1 [%0];" :: "l"(planeH + idC.y));
            asm volatile("prefetch.global.L1 [%0];" :: "l"(planeH + idC.z));
            asm volatile("prefetch.global.L1 [%0];" :: "l"(planeH + idC.w));
        }
        asm volatile("cp.async.wait_group 0;" ::: "memory");
        __syncthreads();
    }

    int tap = 0, ch = 0;
    for (int it = 0; it < 36; ++it) {
        int tapn = tap + 1, chn = ch;
        if (tapn == 9) { tapn = 0; chn = ch + 1; }
        bool hn = (chn < 4);
        int cur = it & 1, nxt = cur ^ 1;
        unsigned aCur = SM_A + (unsigned)(cur << 13);
        unsigned aNxt = SM_A + (unsigned)(nxt << 13);
        unsigned bCur = SM_B + (unsigned)(cur << 15);
        unsigned bNxt = SM_B + (unsigned)(nxt << 15);

        // issue B(next) copy — overlaps the whole iteration
        if (hn) {
            const uint4* src = g_wB + (tapn * 4 + chn) * 2048;
#pragma unroll
            for (int i = 0; i < 8; ++i)
                cp16(sb + bNxt + ((tid + i * 256) << 4), src + tid + i * 256);
            asm volatile("cp.async.commit_group;" ::: "memory");
        }

        // pre-sample t=it+2 and prefetch one full iteration ahead
        int4 idN; float4 wvN;
        int t2 = it + 2;
        bool hn2 = (t2 < 36);
        if (hn2) {
            int tap2 = t2 - (t2 / 9) * 9, ch2 = t2 / 9;
            samp(g_py[gi0 + (tap2 << 12)], g_px[gi0 + (tap2 << 12)], idN, wvN);
            if ((tid & 3) == 0) {
                const __half* pf = planeH + (ch2 << 6);
                asm volatile("prefetch.global.L1 [%0];" :: "l"(pf + idN.x));
                asm volatile("prefetch.global.L1 [%0];" :: "l"(pf + idN.y));
                asm volatile("prefetch.global.L1 [%0];" :: "l"(pf + idN.z));
                asm volatile("prefetch.global.L1 [%0];" :: "l"(pf + idN.w));
            }
        }

        const __half* pbh = planeH + (chn << 6) + cq;
        unsigned long long w0, w1, w2, w3;
        if (hn) { w0 = pack2(wvC.x); w1 = pack2(wvC.y); w2 = pack2(wvC.z); w3 = pack2(wvC.w); }

        // ---- 4 k16-steps; A staging for next iter (carried coords) in ks=0,1 ----
#pragma unroll
        for (int ks = 0; ks < 4; ++ks) {
            uint4 u0, u1, u2, u3;
            bool st = hn && (ks < 2);
            if (st) {
                const __half* p4 = pbh + (ks << 3);
                u0 = *(const uint4*)(p4 + idC.x);
                u1 = *(const uint4*)(p4 + idC.y);
                u2 = *(const uint4*)(p4 + idC.z);
                u3 = *(const uint4*)(p4 + idC.w);
            }
            {
                unsigned a[2][4];
#pragma unroll
                for (int mi = 0; mi < 2; ++mi) {
                    unsigned lin = (aBase + (unsigned)(ks << 5) + (unsigned)(mi << 11)) ^ xorS;
                    ldsm4(a[mi][0], a[mi][1], a[mi][2], a[mi][3], sb + aCur + lin);
                }
#pragma unroll
                for (int nh = 0; nh < 2; ++nh) {
                    unsigned bf[4][2];
#pragma unroll
                    for (int n16 = 0; n16 < 2; ++n16) {
                        unsigned lin = (bBase + (unsigned)(ks << 5) + (unsigned)(nh << 12)
                                        + (unsigned)(n16 << 11)) ^ xorS;
                        unsigned q0, q1, q2, q3;
                        ldsm4(q0, q1, q2, q3, sb + bCur + lin);
                        bf[n16 * 2 + 0][0] = q0; bf[n16 * 2 + 0][1] = q1;
                        bf[n16 * 2 + 1][0] = q2; bf[n16 * 2 + 1][1] = q3;
                    }
#pragma unroll
                    for (int mi = 0; mi < 2; ++mi)
#pragma unroll
                        for (int nf = 0; nf < 4; ++nf)
                            mma16816(acc[mi][nh * 4 + nf], a[mi][0], a[mi][1], a[mi][2], a[mi][3],
                                     bf[nf][0], bf[nf][1]);
                }
            }
            if (st) {
                uint4 stv;
#pragma unroll
                for (int q = 0; q < 4; ++q) {
                    unsigned long long f0 = packf2(__half22float2(((const __half2*)&u0)[q]));
                    unsigned long long f1 = packf2(__half22float2(((const __half2*)&u1)[q]));
                    unsigned long long f2 = packf2(__half22float2(((const __half2*)&u2)[q]));
                    unsigned long long f3 = packf2(__half22float2(((const __half2*)&u3)[q]));
                    unsigned long long s2 = fma2(w0, f0, fma2(w1, f1, fma2(w2, f2, fma2(w3, f3, 0ull))));
                    ((unsigned*)&stv)[q] = h2_from_f2(s2);
                }
                unsigned off = ((unsigned)(mA << 7) + (unsigned)((cq + (ks << 3)) << 1)) ^ xm;
                *(uint4*)(smem + aNxt + off) = stv;
            }
        }
        if (hn2) { idC = idN; wvC = wvN; }
        if (hn) asm volatile("cp.async.wait_group 0;" ::: "memory");
        __syncthreads();
        tap = tapn; ch = chn;
    }

    // ---- epilogue: NCHW scatter from D fragments ----
    {
        int g = lid >> 2, t = lid & 3;
        float* pb = out + ((size_t)b << 20) + (y << 6);
#pragma unroll
        for (int mi = 0; mi < 2; ++mi) {
            int x0p = (warpM << 5) + (mi << 4) + g;
#pragma unroll
            for (int nf = 0; nf < 8; ++nf) {
                int o = (warpN << 6) + (nf << 3) + (t << 1);
                float* p0 = pb + ((size_t)o << 12);
                p0[x0p]            = acc[mi][nf][0];
                p0[4096 + x0p]     = acc[mi][nf][1];
                p0[x0p + 8]        = acc[mi][nf][2];
                p0[4096 + x0p + 8] = acc[mi][nf][3];
            }
        }
    }
}

// ---------------- launch ----------------
extern "C" void kernel_launch(void* const* d_in, const int* in_sizes, int n_in,
                              void* d_out, int out_size) {
    const float* x      = (const float*)d_in[0];
    const float* offw   = (const float*)d_in[1];
    const float* offb   = (const float*)d_in[2];
    const float* conv_w = (const float*)d_in[3];
    float* out = (float*)d_out;

    static int smem_set = 0;
    if (!smem_set) {
        cudaFuncSetAttribute(k_main, cudaFuncAttributeMaxDynamicSharedMemorySize, SM_TOTAL);
        cudaFuncSetAttribute(k_offs, cudaFuncAttributeMaxDynamicSharedMemorySize, OFP_TOT);
        smem_set = 1;
    }

    int prep_blocks = (K9 * 4 * 256 * 64 + 36 * 32 * 64 + 255) / 256;
    k_txp_prep<<<TXP_BLOCKS + prep_blocks, 256>>>(x, conv_w, offw);
    k_offs<<<BB * 32, 256, OFP_TOT>>>(offb);
    k_main<<<BB * HH, 256, SM_TOTAL>>>(out);
}

// round 15
// speedup vs baseline: 1.0512x; 1.0512x over previous
#include <cuda_runtime.h>
#include <cuda_fp16.h>
#include <cuda_bf16.h>
#include <cstdint>

// Problem constants
#define BB 8
#define CC_ 256
#define OO 256
#define HH 64
#define WW 64
#define HWSZ 4096
#define PLANE (HH*WW*CC_)
#define K9 9

// ---------------- scratch (static __device__ — no allocation) ----------------
__device__ float  g_xT[BB * PLANE];           // x in NHWC fp32 (offset conv)
__device__ __half g_xH[BB * PLANE];           // x in NHWC fp16 (gather)
__device__ float g_py[BB * K9 * HWSZ];
__device__ float g_px[BB * K9 * HWSZ];
// main-conv B images, swizzled fp16: [tap*4+ch] -> [o:256][c:64] (32KB each)
__device__ uint4 g_wB[K9 * 4 * 2048];
// offset-conv B images, swizzled bf16 hi/lo: [chunk=tap*4+ch] -> [n:32][k:64] (4KB each)
__device__ uint4 g_oBhi[36 * 256];
__device__ uint4 g_oBlo[36 * 256];

// ---------------- helpers ----------------
__device__ __forceinline__ unsigned smem_u32(const void* p) {
    unsigned a;
    asm("{ .reg .u64 t; cvta.to.shared.u64 t, %1; cvt.u32.u64 %0, t; }" : "=r"(a) : "l"(p));
    return a;
}
__device__ __forceinline__ void ldsm4(unsigned& r0, unsigned& r1, unsigned& r2, unsigned& r3, unsigned addr) {
    asm volatile("ldmatrix.sync.aligned.m8n8.x4.shared.b16 {%0,%1,%2,%3}, [%4];"
                 : "=r"(r0), "=r"(r1), "=r"(r2), "=r"(r3) : "r"(addr));
}
__device__ __forceinline__ void mma16816(float* d, unsigned a0, unsigned a1, unsigned a2, unsigned a3,
                                         unsigned b0, unsigned b1) {
    asm volatile("mma.sync.aligned.m16n8k16.row.col.f32.f16.f16.f32 "
                 "{%0,%1,%2,%3}, {%4,%5,%6,%7}, {%8,%9}, {%0,%1,%2,%3};"
                 : "+f"(d[0]), "+f"(d[1]), "+f"(d[2]), "+f"(d[3])
                 : "r"(a0), "r"(a1), "r"(a2), "r"(a3), "r"(b0), "r"(b1));
}
__device__ __forceinline__ void mma16816bf(float* d, unsigned a0, unsigned a1, unsigned a2, unsigned a3,
                                           unsigned b0, unsigned b1) {
    asm volatile("mma.sync.aligned.m16n8k16.row.col.f32.bf16.bf16.f32 "
                 "{%0,%1,%2,%3}, {%4,%5,%6,%7}, {%8,%9}, {%0,%1,%2,%3};"
                 : "+f"(d[0]), "+f"(d[1]), "+f"(d[2]), "+f"(d[3])
                 : "r"(a0), "r"(a1), "r"(a2), "r"(a3), "r"(b0), "r"(b1));
}
__device__ __forceinline__ void cp16(unsigned dst, const void* src) {
    asm volatile("cp.async.cg.shared.global [%0], [%1], 16;" :: "r"(dst), "l"(src));
}
__device__ __forceinline__ unsigned pack_h2(float a, float b) {
    __half2 t = __floats2half2_rn(a, b);
    return *(unsigned*)&t;
}
__device__ __forceinline__ unsigned pack_bf2(float a, float b) {
    __nv_bfloat162 t; t.x = __float2bfloat16(a); t.y = __float2bfloat16(b);
    return *(unsigned*)&t;
}
__device__ __forceinline__ void samp(float py, float px, int4& id, float4& wv) {
    float fy = floorf(py), fx = floorf(px);
    int iy0 = (int)fy, ix0 = (int)fx;
    float wy1 = py - fy, wx1 = px - fx;
    float wy0 = 1.f - wy1, wx0 = 1.f - wx1;
    int iy1 = iy0 + 1, ix1 = ix0 + 1;
    bool vy0 = (iy0 >= 0) && (iy0 < HH), vy1 = (iy1 >= 0) && (iy1 < HH);
    bool vx0 = (ix0 >= 0) && (ix0 < WW), vx1 = (ix1 >= 0) && (ix1 < WW);
    int cy0 = min(max(iy0, 0), HH - 1), cy1 = min(max(iy1, 0), HH - 1);
    int cx0 = min(max(ix0, 0), WW - 1), cx1 = min(max(ix1, 0), WW - 1);
    id = make_int4(((cy0 << 6) + cx0) << 8, ((cy0 << 6) + cx1) << 8,
                   ((cy1 << 6) + cx0) << 8, ((cy1 << 6) + cx1) << 8);
    wv = make_float4((vy0 && vx0) ? wy0 * wx0 : 0.f, (vy0 && vx1) ? wy0 * wx1 : 0.f,
                     (vy1 && vx0) ? wy1 * wx0 : 0.f, (vy1 && vx1) ? wy1 * wx1 : 0.f);
}

// ---------------- kernel 1: fused NCHW->NHWC transpose (fp32+fp16) + weight prep ----------------
#define TXP_BLOCKS (BB * HH * 2)
__global__ __launch_bounds__(256) void k_txp_prep(const float* __restrict__ x,
                                                  const float* __restrict__ conv_w,
                                                  const float* __restrict__ offw) {
    if (blockIdx.x < TXP_BLOCKS) {
        __shared__ float t[128][65];
        int b = blockIdx.x >> 7;
        int y = (blockIdx.x >> 1) & 63;
        int h = blockIdx.x & 1;
        for (int i = threadIdx.x; i < 128 * 64; i += 256) {
            int c = i >> 6, xx = i & 63;
            t[c][xx] = x[(((b << 8) + (h << 7) + c) << 12) + (y << 6) + xx];
        }
        __syncthreads();
        for (int i = threadIdx.x; i < 64 * 128; i += 256) {
            int xx = i >> 7, c = i & 127;
            float v = t[c][xx];
            size_t o = ((((size_t)(b << 6) + y) << 6) + xx) * 256 + (h << 7) + c;
            g_xT[o] = v;
            g_xH[o] = __float2half_rn(v);
        }
        return;
    }
    int idx = (blockIdx.x - TXP_BLOCKS) * 256 + threadIdx.x;
    if (idx < K9 * 4 * 256 * 64) {
        int c   = idx & 63;
        int o   = (idx >> 6) & 255;
        int ch  = (idx >> 14) & 3;
        int tap = idx >> 16;
        float f = conv_w[(o * 256 + (ch << 6) + c) * 9 + tap];
        int img = tap * 4 + ch;
        unsigned off = (unsigned)((o << 7) + (c << 1));
        off ^= (unsigned)((o & 7) << 4);               // ldmatrix-friendly XOR swizzle
        ((__half*)g_wB)[img * 16384 + (off >> 1)] = __float2half_rn(f);
    }
    int j = idx - K9 * 4 * 256 * 64;
    if (j >= 0 && j < 36 * 32 * 64) {
        int kk    = j & 63;
        int n     = (j >> 6) & 31;
        int chunk = j >> 11;             // tap*4+ch
        int tap   = chunk >> 2;
        int ch    = chunk & 3;
        float f = (n < 18) ? offw[(n * 256 + (ch << 6) + kk) * 9 + tap] : 0.f;
        __nv_bfloat16 hi = __float2bfloat16(f);
        __nv_bfloat16 lo = __float2bfloat16(f - __bfloat162float(hi));
        unsigned off = (unsigned)((n << 7) + (kk << 1));
        off ^= (unsigned)((n & 7) << 4);
        ((__nv_bfloat16*)g_oBhi)[chunk * 2048 + (off >> 1)] = hi;
        ((__nv_bfloat16*)g_oBlo)[chunk * 2048 + (off >> 1)] = lo;
    }
}

// ---------------- kernel 2: offset conv, panel-staged A + 3-pass bf16 HMMA ----------------
// block = (b, row-pair): M=128 px, N=24 used (pad 32), K = 4 ch-chunks x 64.
// A panel: 4 rows x 66 cols x 64ch staged ONCE per ch-chunk; 9 taps read shifted addresses.
#define OFP_HI   0
#define OFP_LO   33792
#define OFP_B    67584
#define OFP_TOT  83968

__global__ __launch_bounds__(256, 2) void k_offs(const float* __restrict__ offb) {
    extern __shared__ char smem[];
    unsigned sb = smem_u32(smem);
    int tid = threadIdx.x;
    int w = tid >> 5, lid = tid & 31;
    int b = blockIdx.x >> 5;
    int y0 = (blockIdx.x & 31) << 1;

    const float* plane = g_xT + ((size_t)b << 20);
    int r = w >> 2;                      // output row within pair
    int cbase = (w & 3) << 4;            // col base of warp's 16-pixel strip
    unsigned xorS = (unsigned)((lid & 7) << 4);
    unsigned bBase = (unsigned)(((lid & 7) + ((lid & 16) ? 8 : 0)) << 7)
                   + (unsigned)(((lid >> 3) & 1) << 4);

    float acc[3][4];
#pragma unroll
    for (int nf = 0; nf < 3; ++nf)
#pragma unroll
        for (int q = 0; q < 4; ++q) acc[nf][q] = 0.f;

    // prologue: B(t=0)
    {
        cp16(sb + OFP_B + (tid << 4), g_oBhi + tid);
        cp16(sb + OFP_B + 4096 + (tid << 4), g_oBlo + tid);
        asm volatile("cp.async.commit_group;" ::: "memory");
    }
    // stage panel for ch=0
    {
        for (int p = tid; p < 264; p += 256) {
            int row = p / 66, col = p - row * 66;
            int yy = y0 - 1 + row, xx = col - 1;
            bool ok = (yy >= 0) && (yy < HH) && (xx >= 0) && (xx < WW);
            const float* src = plane + ((yy << 6) + xx) * 256;
            unsigned pb = (unsigned)(p << 7);
            unsigned sw = (unsigned)((p & 7) << 4);
#pragma unroll
            for (int j = 0; j < 16; ++j) {
                float4 v = ok ? *(const float4*)(src + (j << 2)) : make_float4(0.f, 0.f, 0.f, 0.f);
                __nv_bfloat16 h0 = __float2bfloat16(v.x), h1 = __float2bfloat16(v.y);
                __nv_bfloat16 h2 = __float2bfloat16(v.z), h3 = __float2bfloat16(v.w);
                uint2 uh, ul;
                { __nv_bfloat162 t0; t0.x = h0; t0.y = h1; uh.x = *(unsigned*)&t0;
                  __nv_bfloat162 t1; t1.x = h2; t1.y = h3; uh.y = *(unsigned*)&t1; }
                ul.x = pack_bf2(v.x - __bfloat162float(h0), v.y - __bfloat162float(h1));
                ul.y = pack_bf2(v.z - __bfloat162float(h2), v.w - __bfloat162float(h3));
                unsigned off = pb + (unsigned)((j << 3) ^ sw);
                *(uint2*)(smem + OFP_HI + off) = uh;
                *(uint2*)(smem + OFP_LO + off) = ul;
            }
        }
    }

    for (int t = 0; t < 36; ++t) {
        int ch = t / 9, tap = t - ch * 9;
        // commit B(t+1)
        if (t < 35) {
            int t1 = t + 1;
            int chk = (t1 - (t1 / 9) * 9) * 4 + (t1 / 9);
            unsigned dst = sb + OFP_B + (unsigned)((t1 & 1) << 13);
            cp16(dst + (tid << 4), g_oBhi + chk * 256 + tid);
            cp16(dst + 4096 + (tid << 4), g_oBlo + chk * 256 + tid);
            asm volatile("cp.async.commit_group;" ::: "memory");
        }
        // re-stage panel at each new ch-chunk
        if (tap == 0 && t > 0) {
            __syncthreads();             // all warps done reading old panel
            for (int p = tid; p < 264; p += 256) {
                int row = p / 66, col = p - row * 66;
                int yy = y0 - 1 + row, xx = col - 1;
                bool ok = (yy >= 0) && (yy < HH) && (xx >= 0) && (xx < WW);
                const float* src = plane + ((yy << 6) + xx) * 256 + (ch << 6);
                unsigned pb = (unsigned)(p << 7);
                unsigned sw = (unsigned)((p & 7) << 4);
#pragma unroll
                for (int j = 0; j < 16; ++j) {
                    float4 v = ok ? *(const float4*)(src + (j << 2)) : make_float4(0.f, 0.f, 0.f, 0.f);
                    __nv_bfloat16 h0 = __float2bfloat16(v.x), h1 = __float2bfloat16(v.y);
                    __nv_bfloat16 h2 = __float2bfloat16(v.z), h3 = __float2bfloat16(v.w);
                    uint2 uh, ul;
                    { __nv_bfloat162 t0; t0.x = h0; t0.y = h1; uh.x = *(unsigned*)&t0;
                      __nv_bfloat162 t1; t1.x = h2; t1.y = h3; uh.y = *(unsigned*)&t1; }
                    ul.x = pack_bf2(v.x - __bfloat162float(h0), v.y - __bfloat162float(h1));
                    ul.y = pack_bf2(v.z - __bfloat162float(h2), v.w - __bfloat162float(h3));
                    unsigned off = pb + (unsigned)((j << 3) ^ sw);
                    *(uint2*)(smem + OFP_HI + off) = uh;
                    *(uint2*)(smem + OFP_LO + off) = ul;
                }
            }
        }
        if (t < 35) { asm volatile("cp.async.wait_group 1;" ::: "memory"); }
        else        { asm volatile("cp.async.wait_group 0;" ::: "memory"); }
        __syncthreads();

        // ---- MMAs: 4 k16 steps, 3 passes, nf=0..2 ----
        int ty = tap / 3, tx = tap - ty * 3;
        int tb = (r + ty) * 66 + cbase + tx;
        unsigned bbuf = OFP_B + (unsigned)((t & 1) << 13);
#pragma unroll
        for (int ks = 0; ks < 4; ++ks) {
            unsigned p = (unsigned)(tb + (lid & 15));
            unsigned lin = (p << 7) + (unsigned)(ks << 5) + (unsigned)((lid >> 4) << 4);
            lin ^= (p & 7) << 4;
            unsigned ah0, ah1, ah2, ah3, al0, al1, al2, al3;
            ldsm4(ah0, ah1, ah2, ah3, sb + OFP_HI + lin);
            ldsm4(al0, al1, al2, al3, sb + OFP_LO + lin);
            unsigned bh[4][2], bl[4][2];
#pragma unroll
            for (int n16 = 0; n16 < 2; ++n16) {
                unsigned bln = (bBase + (unsigned)(ks << 5) + (unsigned)(n16 << 11)) ^ xorS;
                unsigned q0, q1, q2, q3;
                ldsm4(q0, q1, q2, q3, sb + bbuf + bln);
                bh[n16 * 2 + 0][0] = q0; bh[n16 * 2 + 0][1] = q1;
                bh[n16 * 2 + 1][0] = q2; bh[n16 * 2 + 1][1] = q3;
                ldsm4(q0, q1, q2, q3, sb + bbuf + 4096 + bln);
                bl[n16 * 2 + 0][0] = q0; bl[n16 * 2 + 0][1] = q1;
                bl[n16 * 2 + 1][0] = q2; bl[n16 * 2 + 1][1] = q3;
            }
#pragma unroll
            for (int nf = 0; nf < 3; ++nf) {
                mma16816bf(acc[nf], ah0, ah1, ah2, ah3, bh[nf][0], bh[nf][1]);
                mma16816bf(acc[nf], ah0, ah1, ah2, ah3, bl[nf][0], bl[nf][1]);
                mma16816bf(acc[nf], al0, al1, al2, al3, bh[nf][0], bh[nf][1]);
            }
        }
    }

    // ---- epilogue: coords = base + offset + bias ----
#pragma unroll
    for (int nf = 0; nf < 3; ++nf) {
        int k = (nf << 2) + (lid & 3);
        if (k < 9) {
            float oy = offb[2 * k], ox = offb[2 * k + 1];
            int ky = k / 3, kx = k - ky * 3;
#pragma unroll
            for (int h = 0; h < 2; ++h) {
                int m = (w << 4) + (lid >> 2) + (h << 3);
                int ym = y0 + (m >> 6), xm = m & 63;
                int gi = ((b * 9 + k) << 12) + (ym << 6) + xm;
                g_py[gi] = (float)(ym - 1 + ky) + acc[nf][h * 2]     + oy;
                g_px[gi] = (float)(xm - 1 + kx) + acc[nf][h * 2 + 1] + ox;
            }
        }
    }
}

// ---------------- kernel 3: fused fp16 gather + single-pass fp16 HMMA GEMM ----------------
// block = (b, y): M=64 pixels, N=256 outputs; 8 warps 2Mx4N, 32x64 warp tiles.
// smem: A double 2x8KB + B double 2x32KB = 80KB; 2 CTAs/SM.
#define SM_A     0
#define SM_B     16384
#define SM_TOTAL 81920

__global__ __launch_bounds__(256, 2) void k_main(float* __restrict__ out) {
    extern __shared__ char smem[];
    unsigned sb = smem_u32(smem);
    int tid = threadIdx.x;
    int w = tid >> 5, lid = tid & 31;
    int b = blockIdx.x >> 6;
    int y = blockIdx.x & 63;

    const __half* planeH = g_xH + ((size_t)b << 20);
    int mA = tid >> 2;                    // staging pixel 0..63
    int cq = (tid & 3) << 4;              // 16-chan strip within 64-chunk
    unsigned xm = (unsigned)((mA & 7) << 4);
    int gi0 = ((b * 9) << 12) + (y << 6) + mA;

    int warpM = w >> 2, warpN = w & 3;
    unsigned xorS  = (unsigned)((lid & 7) << 4);
    unsigned aBase = (unsigned)(((warpM << 5) + (lid & 15)) << 7) + (unsigned)((lid >> 4) << 4);
    unsigned bBase = (unsigned)(((warpN << 6) + (lid & 7) + ((lid & 16) ? 8 : 0)) << 7)
                   + (unsigned)(((lid >> 3) & 1) << 4);

    float acc[2][8][4];
#pragma unroll
    for (int mi = 0; mi < 2; ++mi)
#pragma unroll
        for (int nf = 0; nf < 8; ++nf)
#pragma unroll
            for (int q = 0; q < 4; ++q) acc[mi][nf][q] = 0.f;

    // ---- prologue: stage iter 0 (tap0, ch0) into buffer 0 ----
    {
#pragma unroll
        for (int i = 0; i < 8; ++i)
            cp16(sb + SM_B + ((tid + i * 256) << 4), g_wB + tid + i * 256);
        asm volatile("cp.async.commit_group;" ::: "memory");
        int4 id; float4 wv;
        samp(g_py[gi0], g_px[gi0], id, wv);
        const __half* pbh = planeH + cq;
#pragma unroll
        for (int seg = 0; seg < 2; ++seg) {
            const __half* p4 = pbh + (seg << 3);
            uint4 u0 = *(const uint4*)(p4 + id.x);
            uint4 u1 = *(const uint4*)(p4 + id.y);
            uint4 u2 = *(const uint4*)(p4 + id.z);
            uint4 u3 = *(const uint4*)(p4 + id.w);
            float s[8];
#pragma unroll
            for (int q = 0; q < 4; ++q) {
                float2 f0 = __half22float2(((const __half2*)&u0)[q]);
                float2 f1 = __half22float2(((const __half2*)&u1)[q]);
                float2 f2 = __half22float2(((const __half2*)&u2)[q]);
                float2 f3 = __half22float2(((const __half2*)&u3)[q]);
                s[2 * q]     = wv.x * f0.x + wv.y * f1.x + wv.z * f2.x + wv.w * f3.x;
                s[2 * q + 1] = wv.x * f0.y + wv.y * f1.y + wv.z * f2.y + wv.w * f3.y;
            }
            unsigned off = ((unsigned)(mA << 7) + (unsigned)((cq + (seg << 3)) << 1)) ^ xm;
            uint4 st;
            st.x = pack_h2(s[0], s[1]); st.y = pack_h2(s[2], s[3]);
            st.z = pack_h2(s[4], s[5]); st.w = pack_h2(s[6], s[7]);
            *(uint4*)(smem + SM_A + off) = st;
        }
        asm volatile("cp.async.wait_group 0;" ::: "memory");
        __syncthreads();
    }

    int tap = 0, ch = 0;
    for (int it = 0; it < 36; ++it) {
        int tapn = tap + 1, chn = ch;
        if (tapn == 9) { tapn = 0; chn = ch + 1; }
        bool hn = (chn < 4);
        int cur = it & 1, nxt = cur ^ 1;
        unsigned aCur = SM_A + (unsigned)(cur << 13);
        unsigned aNxt = SM_A + (unsigned)(nxt << 13);
        unsigned bCur = SM_B + (unsigned)(cur << 15);
        unsigned bNxt = SM_B + (unsigned)(nxt << 15);

        // issue B(next) copy — overlaps the whole iteration
        if (hn) {
            const uint4* src = g_wB + (tapn * 4 + chn) * 2048;
#pragma unroll
            for (int i = 0; i < 8; ++i)
                cp16(sb + bNxt + ((tid + i * 256) << 4), src + tid + i * 256);
            asm volatile("cp.async.commit_group;" ::: "memory");
        }

        int4 id; float4 wv;
        const __half* pbh = planeH;
        if (hn) {
            samp(g_py[gi0 + (tapn << 12)], g_px[gi0 + (tapn << 12)], id, wv);
            pbh = planeH + (chn << 6) + cq;
            // prefetch the 4 corner lines (one lane per pixel; each chunk = one 128B line)
            if ((tid & 3) == 0) {
                const __half* pf = planeH + (chn << 6);
                asm volatile("prefetch.global.L1 [%0];" :: "l"(pf + id.x));
                asm volatile("prefetch.global.L1 [%0];" :: "l"(pf + id.y));
                asm volatile("prefetch.global.L1 [%0];" :: "l"(pf + id.z));
                asm volatile("prefetch.global.L1 [%0];" :: "l"(pf + id.w));
            }
        }

        // ---- 4 k16-steps; A staging for next iter interleaved with ks=0,1 ----
#pragma unroll
        for (int ks = 0; ks < 4; ++ks) {
            uint4 u0, u1, u2, u3;
            bool st = hn && (ks < 2);
            if (st) {
                const __half* p4 = pbh + (ks << 3);
                u0 = *(const uint4*)(p4 + id.x);
                u1 = *(const uint4*)(p4 + id.y);
                u2 = *(const uint4*)(p4 + id.z);
                u3 = *(const uint4*)(p4 + id.w);
            }
            {
                unsigned a[2][4];
#pragma unroll
                for (int mi = 0; mi < 2; ++mi) {
                    unsigned lin = (aBase + (unsigned)(ks << 5) + (unsigned)(mi << 11)) ^ xorS;
                    ldsm4(a[mi][0], a[mi][1], a[mi][2], a[mi][3], sb + aCur + lin);
                }
#pragma unroll
                for (int nh = 0; nh < 2; ++nh) {
                    unsigned bf[4][2];
#pragma unroll
                    for (int n16 = 0; n16 < 2; ++n16) {
                        unsigned lin = (bBase + (unsigned)(ks << 5) + (unsigned)(nh << 12)
                                        + (unsigned)(n16 << 11)) ^ xorS;
                        unsigned q0, q1, q2, q3;
                        ldsm4(q0, q1, q2, q3, sb + bCur + lin);
                        bf[n16 * 2 + 0][0] = q0; bf[n16 * 2 + 0][1] = q1;
                        bf[n16 * 2 + 1][0] = q2; bf[n16 * 2 + 1][1] = q3;
                    }
#pragma unroll
                    for (int mi = 0; mi < 2; ++mi)
#pragma unroll
                        for (int nf = 0; nf < 4; ++nf)
                            mma16816(acc[mi][nh * 4 + nf], a[mi][0], a[mi][1], a[mi][2], a[mi][3],
                                     bf[nf][0], bf[nf][1]);
                }
            }
            if (st) {
                float s[8];
#pragma unroll
                for (int q = 0; q < 4; ++q) {
                    float2 f0 = __half22float2(((const __half2*)&u0)[q]);
                    float2 f1 = __half22float2(((const __half2*)&u1)[q]);
                    float2 f2 = __half22float2(((const __half2*)&u2)[q]);
                    float2 f3 = __half22float2(((const __half2*)&u3)[q]);
                    s[2 * q]     = wv.x * f0.x + wv.y * f1.x + wv.z * f2.x + wv.w * f3.x;
                    s[2 * q + 1] = wv.x * f0.y + wv.y * f1.y + wv.z * f2.y + wv.w * f3.y;
                }
                unsigned off = ((unsigned)(mA << 7) + (unsigned)((cq + (ks << 3)) << 1)) ^ xm;
                uint4 stv;
                stv.x = pack_h2(s[0], s[1]); stv.y = pack_h2(s[2], s[3]);
                stv.z = pack_h2(s[4], s[5]); stv.w = pack_h2(s[6], s[7]);
                *(uint4*)(smem + aNxt + off) = stv;
            }
        }
        if (hn) asm volatile("cp.async.wait_group 0;" ::: "memory");
        __syncthreads();
        tap = tapn; ch = chn;
    }

    // ---- epilogue: NCHW scatter from D fragments ----
    {
        int g = lid >> 2, t = lid & 3;
        float* pb = out + ((size_t)b << 20) + (y << 6);
#pragma unroll
        for (int mi = 0; mi < 2; ++mi) {
            int x0p = (warpM << 5) + (mi << 4) + g;
#pragma unroll
            for (int nf = 0; nf < 8; ++nf) {
                int o = (warpN << 6) + (nf << 3) + (t << 1);
                float* p0 = pb + ((size_t)o << 12);
                p0[x0p]            = acc[mi][nf][0];
                p0[4096 + x0p]     = acc[mi][nf][1];
                p0[x0p + 8]        = acc[mi][nf][2];
                p0[4096 + x0p + 8] = acc[mi][nf][3];
            }
        }
    }
}

// ---------------- launch ----------------
extern "C" void kernel_launch(void* const* d_in, const int* in_sizes, int n_in,
                              void* d_out, int out_size) {
    const float* x      = (const float*)d_in[0];
    const float* offw   = (const float*)d_in[1];
    const float* offb   = (const float*)d_in[2];
    const float* conv_w = (const float*)d_in[3];
    float* out = (float*)d_out;

    static int smem_set = 0;
    if (!smem_set) {
        cudaFuncSetAttribute(k_main, cudaFuncAttributeMaxDynamicSharedMemorySize, SM_TOTAL);
        cudaFuncSetAttribute(k_offs, cudaFuncAttributeMaxDynamicSharedMemorySize, OFP_TOT);
        smem_set = 1;
    }

    int prep_blocks = (K9 * 4 * 256 * 64 + 36 * 32 * 64 + 255) / 256;
    k_txp_prep<<<TXP_BLOCKS + prep_blocks, 256>>>(x, conv_w, offw);
    k_offs<<<BB * 32, 256, OFP_TOT>>>(offb);
    k_main<<<BB * HH, 256, SM_TOTAL>>>(out);
}